// round 2
// baseline (speedup 1.0000x reference)
#include <cuda_runtime.h>
#include <stdint.h>

#define NPTS 8192
#define NWORDS 128            // NPTS / 64 uint64 words per mask row
#define RAD2 64.0f            // radius^2 (radius = 8.0)

// ---- device scratch (no allocations allowed) ----
__device__ float    g_sx[NPTS];             // sorted coords x (coords[...,0])
__device__ float    g_sy[NPTS];             // sorted coords y (coords[...,1])
__device__ float    g_ss[NPTS];             // sorted scores
__device__ int      g_order[NPTS];          // sorted -> original index
__device__ unsigned long long g_mask[(size_t)NPTS * NWORDS];  // 8 MB suppression bits

// Monotone map: floats compare like these uint32s (ascending).
__device__ __forceinline__ uint32_t f2mono(float f) {
    uint32_t b = __float_as_uint(f);
    return b ^ ((b & 0x80000000u) ? 0xFFFFFFFFu : 0x80000000u);
}

// ============================================================
// K1: stable descending rank by counting (O(N^2), parallel),
//     then scatter sorted coords/scores/order.
//     rank_i = #{ j : m_j > m_i  ||  (m_j == m_i && j < i) }
// grid: NPTS/256 blocks x 256 threads
// ============================================================
__global__ void rank_sort_kernel(const float* __restrict__ coords,
                                 const float* __restrict__ scores) {
    const int tid = threadIdx.x;
    const int i   = blockIdx.x * 256 + tid;
    const uint32_t mi = f2mono(scores[i]);

    __shared__ uint32_t s_m[256];
    int rank = 0;
    for (int t = 0; t < NPTS / 256; ++t) {
        const int j0 = t * 256;
        s_m[tid] = f2mono(scores[j0 + tid]);
        __syncthreads();
        #pragma unroll 8
        for (int jj = 0; jj < 256; ++jj) {
            const uint32_t mj = s_m[jj];
            const int j = j0 + jj;
            rank += (mj > mi) || (mj == mi && j < i);
        }
        __syncthreads();
    }
    // rank is a permutation (tie-break makes keys unique)
    g_order[rank] = i;
    g_ss[rank]    = scores[i];
    g_sx[rank]    = coords[2 * i + 0];
    g_sy[rank]    = coords[2 * i + 1];
}

// ============================================================
// K2: suppression bit tiles. Block = 64 rows x 64 cols.
//     bit b of g_mask[i*128 + cb] = (j > i) && dist(i,j)^2 < RAD2,
//     j = cb*64 + b. All tiles written every launch (lower triangle -> 0).
// grid: (128 colblocks, 128 rowblocks) x 64 threads
// ============================================================
__global__ void mask_kernel() {
    const int cb  = blockIdx.x;
    const int rb  = blockIdx.y;
    const int tid = threadIdx.x;

    __shared__ float cx[64], cy[64];
    {
        const int j = cb * 64 + tid;
        cx[tid] = g_sx[j];
        cy[tid] = g_sy[j];
    }
    __syncthreads();

    const int i = rb * 64 + tid;
    const float xi = g_sx[i];
    const float yi = g_sy[i];

    unsigned long long bits = 0ull;
    #pragma unroll
    for (int b = 0; b < 64; ++b) {
        const int j = cb * 64 + b;
        const float dx = xi - cx[b];
        const float dy = yi - cy[b];
        const float d2 = dx * dx + dy * dy;
        if (j > i && d2 < RAD2) bits |= (1ull << b);
    }
    g_mask[(size_t)i * NWORDS + cb] = bits;
}

// ============================================================
// K3: sequential greedy sweep + output.
//     1 block, 128 threads; thread t owns remv word t (64 columns).
//     Chunked by 64 rows: diagonal word resolved serially by thread c
//     (over shared-prefetched diag column), off-diagonal ORs parallel.
// ============================================================
__global__ void sweep_kernel(float* __restrict__ out, int out_size) {
    const int t = threadIdx.x;
    unsigned long long remv = 0ull;

    __shared__ unsigned long long s_diag[64];
    __shared__ unsigned long long s_kb;
    __shared__ unsigned long long s_remv[NWORDS];

    for (int c = 0; c < NWORDS; ++c) {
        // prefetch diagonal column of this chunk (independent loads)
        if (t < 64)
            s_diag[t] = g_mask[(size_t)(c * 64 + t) * NWORDS + c];
        __syncthreads();

        if (t == c) {
            unsigned long long r = remv, kb = 0ull;
            #pragma unroll
            for (int b = 0; b < 64; ++b) {
                if (!((r >> b) & 1ull)) {
                    kb |= (1ull << b);
                    r  |= s_diag[b];
                }
            }
            remv = r;
            s_kb = kb;
        }
        __syncthreads();

        const unsigned long long kb = s_kb;
        if (t != c) {
            const size_t base = (size_t)c * 64 * NWORDS + t;
            #pragma unroll 8
            for (int b = 0; b < 64; ++b) {
                if ((kb >> b) & 1ull)
                    remv |= g_mask[base + (size_t)b * NWORDS];
            }
        }
        __syncthreads();
    }

    s_remv[t] = remv;
    __syncthreads();

    // outputs: [keep_orig (as 0/1 float, original order), suppressed_scores (sorted order)]
    for (int i = t; i < NPTS; i += 128) {
        const bool kept = !((s_remv[i >> 6] >> (i & 63)) & 1ull);
        const int  o    = g_order[i];
        if (out_size >= 2 * NPTS) {
            out[o]        = kept ? 1.0f : 0.0f;
            out[NPTS + i] = kept ? g_ss[i] : 0.0f;
        } else {
            // fallback: single output = keep mask in original order
            out[o] = kept ? 1.0f : 0.0f;
        }
    }
}

extern "C" void kernel_launch(void* const* d_in, const int* in_sizes, int n_in,
                              void* d_out, int out_size) {
    const float* coords = (const float*)d_in[0];  // [N,2] f32
    const float* scores = (const float*)d_in[1];  // [N]   f32
    float* out = (float*)d_out;

    rank_sort_kernel<<<NPTS / 256, 256>>>(coords, scores);

    dim3 mg(NWORDS, NWORDS);
    mask_kernel<<<mg, 64>>>();

    sweep_kernel<<<1, 128>>>(out, out_size);
}

// round 3
// speedup vs baseline: 2.2601x; 2.2601x over previous
#include <cuda_runtime.h>
#include <stdint.h>

#define NPTS   8192
#define NWORDS 128            // NPTS / 64 uint64 words per mask row
#define RAD2   64.0f          // radius^2 (radius = 8.0)
#define SPLIT  16             // j-dimension split for rank counting

typedef unsigned long long ull;

// ---- device scratch (no allocations allowed) ----
__device__ float g_sx[NPTS];
__device__ float g_sy[NPTS];
__device__ float g_ss[NPTS];
__device__ int   g_order[NPTS];
__device__ int   g_partial[SPLIT][NPTS];                 // partial ranks
__device__ ull   g_mask[(size_t)NPTS * NWORDS];          // 8 MB suppression bits

__device__ __forceinline__ uint32_t f2mono(float f) {
    uint32_t b = __float_as_uint(f);
    return b ^ ((b & 0x80000000u) ? 0xFFFFFFFFu : 0x80000000u);
}

// ============================================================
// K1a: partial stable-descending rank counts.
// grid (32, SPLIT) x 256. Block (bx,by): i = bx*256+t, j-window
// [by*512, by*512+512). partial = #{ j in window : key_j > key_i
//                                    || (key_j == key_i && j < i) }
// ============================================================
__global__ void rank_partial_kernel(const float* __restrict__ scores) {
    const int tid = threadIdx.x;
    const int i   = blockIdx.x * 256 + tid;
    const int by  = blockIdx.y;
    const uint32_t mi = f2mono(scores[i]);

    __shared__ uint32_t s_m[256];
    int cnt = 0;
    #pragma unroll
    for (int tile = 0; tile < (NPTS / SPLIT) / 256; ++tile) {   // 2 tiles of 256
        const int j0 = by * (NPTS / SPLIT) + tile * 256;
        s_m[tid] = f2mono(scores[j0 + tid]);
        __syncthreads();
        #pragma unroll 16
        for (int jj = 0; jj < 256; ++jj) {
            const uint32_t mj = s_m[jj];
            const int j = j0 + jj;
            cnt += (mj > mi) || (mj == mi && j < i);
        }
        __syncthreads();
    }
    g_partial[by][i] = cnt;
}

// ============================================================
// K1b: combine partials -> rank, scatter sorted arrays.
// grid 32 x 256
// ============================================================
__global__ void rank_scatter_kernel(const float* __restrict__ coords,
                                    const float* __restrict__ scores) {
    const int i = blockIdx.x * 256 + threadIdx.x;
    int rank = 0;
    #pragma unroll
    for (int s = 0; s < SPLIT; ++s) rank += g_partial[s][i];
    g_order[rank] = i;
    g_ss[rank]    = scores[i];
    g_sx[rank]    = coords[2 * i + 0];
    g_sy[rank]    = coords[2 * i + 1];
}

// ============================================================
// K2: suppression bit tiles (upper triangle only; lower-tri
// words are never read by the sweep).
// grid (128 colblocks, 128 rowblocks) x 64 threads
// ============================================================
__global__ void mask_kernel() {
    const int cb = blockIdx.x;
    const int rb = blockIdx.y;
    if (cb < rb) return;                       // lower triangle never read
    const int tid = threadIdx.x;

    __shared__ float cx[64], cy[64];
    {
        const int j = cb * 64 + tid;
        cx[tid] = g_sx[j];
        cy[tid] = g_sy[j];
    }
    __syncthreads();

    const int i = rb * 64 + tid;
    const float xi = g_sx[i];
    const float yi = g_sy[i];

    ull bits = 0ull;
    #pragma unroll
    for (int b = 0; b < 64; ++b) {
        const int j = cb * 64 + b;
        const float dx = xi - cx[b];
        const float dy = yi - cy[b];
        const float d2 = dx * dx + dy * dy;
        if (j > i && d2 < RAD2) bits |= (1ull << b);
    }
    g_mask[(size_t)i * NWORDS + cb] = bits;
}

// ============================================================
// K3: sequential greedy sweep + output. 1 block x 128 threads.
// Thread t owns remv word t. Per 64-row chunk c:
//   - every thread t>=c loads the chunk's column word t into
//     64 registers (coalesced, independent -> one L2 latency wave)
//   - thread c resolves the greedy serially from its OWN v[]
//     (static register indexing, no shared diag, no spills)
//   - threads t>c OR kept rows from registers (predicated ALU)
// ============================================================
__global__ void __launch_bounds__(128, 1)
sweep_kernel(float* __restrict__ out, int out_size) {
    const int t = threadIdx.x;
    ull remv = 0ull;
    ull v[64];

    __shared__ ull s_kb;
    __shared__ ull s_remv[NWORDS];

    for (int c = 0; c < NWORDS; ++c) {
        if (t >= c) {
            const ull* base = &g_mask[(size_t)(c * 64) * NWORDS + t];
            #pragma unroll
            for (int b = 0; b < 64; ++b)
                v[b] = base[(size_t)b * NWORDS];
        }

        if (t == c) {
            ull r = remv, kb = 0ull;
            #pragma unroll
            for (int b = 0; b < 64; ++b) {
                if (!((r >> b) & 1ull)) {
                    kb |= (1ull << b);
                    r  |= v[b];
                }
            }
            remv = r;
            s_kb = kb;
        }
        __syncthreads();

        if (t > c) {
            const ull kb = s_kb;
            #pragma unroll
            for (int b = 0; b < 64; ++b) {
                if ((kb >> b) & 1ull) remv |= v[b];
            }
        }
        __syncthreads();                       // protect s_kb for next chunk
    }

    s_remv[t] = remv;
    __syncthreads();

    // outputs: [keep_orig (0/1 float, original order), suppressed_scores (sorted order)]
    for (int i = t; i < NPTS; i += 128) {
        const bool kept = !((s_remv[i >> 6] >> (i & 63)) & 1ull);
        const int  o    = g_order[i];
        if (out_size >= 2 * NPTS) {
            out[o]        = kept ? 1.0f : 0.0f;
            out[NPTS + i] = kept ? g_ss[i] : 0.0f;
        } else {
            out[o] = kept ? 1.0f : 0.0f;
        }
    }
}

extern "C" void kernel_launch(void* const* d_in, const int* in_sizes, int n_in,
                              void* d_out, int out_size) {
    const float* coords = (const float*)d_in[0];  // [N,2] f32
    const float* scores = (const float*)d_in[1];  // [N]   f32
    float* out = (float*)d_out;

    dim3 rg(NPTS / 256, SPLIT);
    rank_partial_kernel<<<rg, 256>>>(scores);
    rank_scatter_kernel<<<NPTS / 256, 256>>>(coords, scores);

    dim3 mg(NWORDS, NWORDS);
    mask_kernel<<<mg, 64>>>();

    sweep_kernel<<<1, 128>>>(out, out_size);
}